// round 7
// baseline (speedup 1.0000x reference)
#include <cuda_runtime.h>
#include <cuda_fp16.h>
#include <cstdint>

#define BB 2
#define DD 64
#define MAXN 50000
#define MAXE 800000
#define SCAN_B 1024

// ---------------- static device scratch (no allocations allowed) -----------
__device__ uint2 g_Ph[(size_t)MAXN * 32];      // fp16 P, [node][batch][64]
__device__ int   g_deg[MAXN];
__device__ int   g_off[MAXN + 1];
__device__ int   g_carry[64];
__device__ int   g_flag[64];
__device__ uint2 g_rank[MAXE];                 // (rank_u, rank_v) per edge
__device__ uint2 g_adj[2 * MAXE];              // (nbr, gate-bits)

// ---------------- small helpers ---------------------------------------------
__device__ __forceinline__ unsigned long long pack2(float lo, float hi) {
    unsigned long long r;
    asm("mov.b64 %0, {%1, %2};" : "=l"(r) : "f"(lo), "f"(hi));
    return r;
}
__device__ __forceinline__ float2 unpack2(unsigned long long v) {
    float2 r;
    asm("mov.b64 {%0, %1}, %2;" : "=f"(r.x), "=f"(r.y) : "l"(v));
    return r;
}
__device__ __forceinline__ void ffma2(unsigned long long& d,
                                      unsigned long long a,
                                      unsigned long long b) {
    asm("fma.rn.f32x2 %0, %1, %2, %0;" : "+l"(d) : "l"(a), "l"(b));
}
__device__ __forceinline__ unsigned pack_h2(float a, float b) {
    __half2 h = __floats2half2_rn(a, b);
    return *reinterpret_cast<unsigned*>(&h);
}
__device__ __forceinline__ float2 unpack_h2(unsigned u) {
    __half2 h = *reinterpret_cast<__half2*>(&u);
    return __half22float2(h);
}

// ---------------------------------------------------------------------------
// Phase 1 (merged launch): blocks [0, nTransB) run the GEMM transform,
// blocks [nTransB, ...) run count+rank. Independent work, co-scheduled.
// ---------------------------------------------------------------------------
__global__ __launch_bounds__(256)
void k_phase1(const float* __restrict__ prev, const float* __restrict__ W,
              const int* __restrict__ edges,
              int nRows, int N, int E, int nTransB)
{
    __shared__ float As[64][66];
    __shared__ float Wt[64][64];

    int tid = threadIdx.x;

    if (blockIdx.x >= nTransB) {
        // ----------------- count + rank (single atomic pass) ---------------
        int i = (blockIdx.x - nTransB) * 256 + tid;
        int Eh = E >> 1;
        if (i < Eh) {
            int4 e2 = reinterpret_cast<const int4*>(edges)[i];
            unsigned r0 = atomicAdd(&g_deg[e2.x], 1);
            unsigned r1 = atomicAdd(&g_deg[e2.y], 1);
            unsigned r2 = atomicAdd(&g_deg[e2.z], 1);
            unsigned r3 = atomicAdd(&g_deg[e2.w], 1);
            reinterpret_cast<uint4*>(g_rank)[i] = make_uint4(r0, r1, r2, r3);
        } else if (i == Eh && (E & 1)) {
            int e = E - 1;
            int u = edges[2 * (size_t)e];
            int v = edges[2 * (size_t)e + 1];
            unsigned ru = atomicAdd(&g_deg[u], 1);
            unsigned rv = atomicAdd(&g_deg[v], 1);
            g_rank[e] = make_uint2(ru, rv);
        }
        return;
    }

    // --------------------- transform: P = prev @ W^T -----------------------
    if (blockIdx.x == 0 && tid < 64) g_flag[tid] = 0;   // reset scan flags

    int row0 = blockIdx.x * 64;

#pragma unroll
    for (int j = 0; j < 4; j++) {
        int f4 = tid + j * 256;
        int e = f4 >> 4, k4 = f4 & 15;
        float4 w = reinterpret_cast<const float4*>(W)[f4];
        Wt[k4 * 4 + 0][e] = w.x;
        Wt[k4 * 4 + 1][e] = w.y;
        Wt[k4 * 4 + 2][e] = w.z;
        Wt[k4 * 4 + 3][e] = w.w;
    }
#pragma unroll
    for (int j = 0; j < 4; j++) {
        int f4 = tid + j * 256;
        int r = f4 >> 4, c4 = f4 & 15;
        float4 a = make_float4(0.f, 0.f, 0.f, 0.f);
        if (row0 + r < nRows)
            a = reinterpret_cast<const float4*>(prev)[(size_t)(row0 + r) * 16 + c4];
        As[c4 * 4 + 0][r] = a.x;
        As[c4 * 4 + 1][r] = a.y;
        As[c4 * 4 + 2][r] = a.z;
        As[c4 * 4 + 3][r] = a.w;
    }
    __syncthreads();

    int colg = tid & 15;
    int rowg = tid >> 4;

    unsigned long long acc[2][4] = {};

#pragma unroll 8
    for (int k = 0; k < 64; k++) {
        const unsigned long long* ar =
            reinterpret_cast<const unsigned long long*>(&As[k][rowg * 4]);
        unsigned long long A0 = ar[0];
        unsigned long long A1 = ar[1];
        float4 w = *reinterpret_cast<const float4*>(&Wt[k][colg * 4]);
        unsigned long long w0 = pack2(w.x, w.x);
        unsigned long long w1 = pack2(w.y, w.y);
        unsigned long long w2 = pack2(w.z, w.z);
        unsigned long long w3 = pack2(w.w, w.w);
        ffma2(acc[0][0], A0, w0); ffma2(acc[0][1], A0, w1);
        ffma2(acc[0][2], A0, w2); ffma2(acc[0][3], A0, w3);
        ffma2(acc[1][0], A1, w0); ffma2(acc[1][1], A1, w1);
        ffma2(acc[1][2], A1, w2); ffma2(acc[1][3], A1, w3);
    }

#pragma unroll
    for (int p = 0; p < 2; p++) {
        float2 v0 = unpack2(acc[p][0]);
        float2 v1 = unpack2(acc[p][1]);
        float2 v2 = unpack2(acc[p][2]);
        float2 v3 = unpack2(acc[p][3]);
        int rA = row0 + rowg * 4 + p * 2;
        int rB = rA + 1;
        if (rA < nRows) {
            int b = (rA >= N) ? 1 : 0;
            int n = rA - b * N;
            g_Ph[(size_t)n * 32 + b * 16 + colg] =
                make_uint2(pack_h2(v0.x, v1.x), pack_h2(v2.x, v3.x));
        }
        if (rB < nRows) {
            int b = (rB >= N) ? 1 : 0;
            int n = rB - b * N;
            g_Ph[(size_t)n * 32 + b * 16 + colg] =
                make_uint2(pack_h2(v0.y, v1.y), pack_h2(v2.y, v3.y));
        }
    }
}

// ---------------------------------------------------------------------------
// Single-launch chained exclusive scan of g_deg -> absolute g_off.
// <=64 blocks, single wave on 148 SMs -> spin-wait on predecessor is safe.
// ---------------------------------------------------------------------------
__global__ __launch_bounds__(SCAN_B)
void k_scan(int N)
{
    __shared__ int wsum[32];
    __shared__ int s_prefix;

    int t = threadIdx.x, lane = t & 31, w = t >> 5;
    int i = blockIdx.x * SCAN_B + t;
    int d = (i < N) ? g_deg[i] : 0;

    int x = d;
#pragma unroll
    for (int s = 1; s < 32; s <<= 1) {
        int y = __shfl_up_sync(0xffffffffu, x, s);
        if (lane >= s) x += y;
    }
    if (lane == 31) wsum[w] = x;
    __syncthreads();
    if (w == 0) {
        int ws = wsum[lane];
#pragma unroll
        for (int s = 1; s < 32; s <<= 1) {
            int y = __shfl_up_sync(0xffffffffu, ws, s);
            if (lane >= s) ws += y;
        }
        wsum[lane] = ws;
    }
    __syncthreads();

    int blockSum = wsum[31];
    if (t == 0) {
        int p = 0;
        if (blockIdx.x > 0) {
            while (atomicAdd(&g_flag[blockIdx.x - 1], 0) == 0) {}
            p = g_carry[blockIdx.x - 1];
        }
        g_carry[blockIdx.x] = p + blockSum;
        __threadfence();
        atomicExch(&g_flag[blockIdx.x], 1);
        s_prefix = p;
    }
    __syncthreads();

    int base = s_prefix + ((w > 0) ? wsum[w - 1] : 0);
    if (i < N) g_off[i] = base + x - d;            // absolute exclusive
    if (blockIdx.x == gridDim.x - 1 && t == SCAN_B - 1)
        g_off[N] = s_prefix + blockSum;
}

// ---------------------------------------------------------------------------
// Atomic-free fill, 2 edges per thread.
// ---------------------------------------------------------------------------
__global__ __launch_bounds__(256)
void k_fill(const int* __restrict__ edges, const float* __restrict__ status,
            int E)
{
    int i = blockIdx.x * blockDim.x + threadIdx.x;
    int Eh = E >> 1;
    if (i < Eh) {
        int4  e2 = reinterpret_cast<const int4*>(edges)[i];
        uint4 r2 = reinterpret_cast<const uint4*>(g_rank)[i];
        float2 st = reinterpret_cast<const float2*>(status)[i];
        unsigned g0 = __float_as_uint(st.x);
        unsigned g1 = __float_as_uint(st.y);
        int o0 = g_off[e2.x] + (int)r2.x;
        int o1 = g_off[e2.y] + (int)r2.y;
        int o2 = g_off[e2.z] + (int)r2.z;
        int o3 = g_off[e2.w] + (int)r2.w;
        g_adj[o0] = make_uint2((unsigned)e2.y, g0);
        g_adj[o1] = make_uint2((unsigned)e2.x, g0);
        g_adj[o2] = make_uint2((unsigned)e2.w, g1);
        g_adj[o3] = make_uint2((unsigned)e2.z, g1);
    } else if (i == Eh && (E & 1)) {
        int e = E - 1;
        int u = edges[2 * (size_t)e];
        int v = edges[2 * (size_t)e + 1];
        uint2 r = g_rank[e];
        unsigned gb = __float_as_uint(status[e]);
        g_adj[g_off[u] + (int)r.x] = make_uint2((unsigned)v, gb);
        g_adj[g_off[v] + (int)r.y] = make_uint2((unsigned)u, gb);
    }
}

// ---------------------------------------------------------------------------
// Gather + epilogue: one warp per node, 8 loads in flight per iteration.
// ---------------------------------------------------------------------------
__global__ __launch_bounds__(256)
void k_gather_final(const float* __restrict__ nodef,
                    const float* __restrict__ edgef,
                    float* __restrict__ out, int N)
{
    int node = (blockIdx.x * blockDim.x + threadIdx.x) >> 5;
    if (node >= N) return;
    int lane = threadIdx.x & 31;

    int beg = __ldg(&g_off[node]);
    int end = __ldg(&g_off[node + 1]);

    float4 acc0 = make_float4(0.f, 0.f, 0.f, 0.f);
    float4 acc1 = make_float4(0.f, 0.f, 0.f, 0.f);
    float4 acc2 = make_float4(0.f, 0.f, 0.f, 0.f);
    float4 acc3 = make_float4(0.f, 0.f, 0.f, 0.f);

    int e = beg;
    for (; e + 7 < end; e += 8) {
        uint2 a0 = g_adj[e];
        uint2 a1 = g_adj[e + 1];
        uint2 a2 = g_adj[e + 2];
        uint2 a3 = g_adj[e + 3];
        uint2 a4 = g_adj[e + 4];
        uint2 a5 = g_adj[e + 5];
        uint2 a6 = g_adj[e + 6];
        uint2 a7 = g_adj[e + 7];
        uint2 q0 = __ldg(g_Ph + (size_t)a0.x * 32 + lane);
        uint2 q1 = __ldg(g_Ph + (size_t)a1.x * 32 + lane);
        uint2 q2 = __ldg(g_Ph + (size_t)a2.x * 32 + lane);
        uint2 q3 = __ldg(g_Ph + (size_t)a3.x * 32 + lane);
        uint2 q4 = __ldg(g_Ph + (size_t)a4.x * 32 + lane);
        uint2 q5 = __ldg(g_Ph + (size_t)a5.x * 32 + lane);
        uint2 q6 = __ldg(g_Ph + (size_t)a6.x * 32 + lane);
        uint2 q7 = __ldg(g_Ph + (size_t)a7.x * 32 + lane);
        float g0 = __uint_as_float(a0.y);
        float g1 = __uint_as_float(a1.y);
        float g2 = __uint_as_float(a2.y);
        float g3 = __uint_as_float(a3.y);
        float g4 = __uint_as_float(a4.y);
        float g5 = __uint_as_float(a5.y);
        float g6 = __uint_as_float(a6.y);
        float g7 = __uint_as_float(a7.y);
        {
            float2 f01 = unpack_h2(q0.x), f23 = unpack_h2(q0.y);
            acc0.x += f01.x * g0; acc0.y += f01.y * g0;
            acc0.z += f23.x * g0; acc0.w += f23.y * g0;
        }
        {
            float2 f01 = unpack_h2(q1.x), f23 = unpack_h2(q1.y);
            acc1.x += f01.x * g1; acc1.y += f01.y * g1;
            acc1.z += f23.x * g1; acc1.w += f23.y * g1;
        }
        {
            float2 f01 = unpack_h2(q2.x), f23 = unpack_h2(q2.y);
            acc2.x += f01.x * g2; acc2.y += f01.y * g2;
            acc2.z += f23.x * g2; acc2.w += f23.y * g2;
        }
        {
            float2 f01 = unpack_h2(q3.x), f23 = unpack_h2(q3.y);
            acc3.x += f01.x * g3; acc3.y += f01.y * g3;
            acc3.z += f23.x * g3; acc3.w += f23.y * g3;
        }
        {
            float2 f01 = unpack_h2(q4.x), f23 = unpack_h2(q4.y);
            acc0.x += f01.x * g4; acc0.y += f01.y * g4;
            acc0.z += f23.x * g4; acc0.w += f23.y * g4;
        }
        {
            float2 f01 = unpack_h2(q5.x), f23 = unpack_h2(q5.y);
            acc1.x += f01.x * g5; acc1.y += f01.y * g5;
            acc1.z += f23.x * g5; acc1.w += f23.y * g5;
        }
        {
            float2 f01 = unpack_h2(q6.x), f23 = unpack_h2(q6.y);
            acc2.x += f01.x * g6; acc2.y += f01.y * g6;
            acc2.z += f23.x * g6; acc2.w += f23.y * g6;
        }
        {
            float2 f01 = unpack_h2(q7.x), f23 = unpack_h2(q7.y);
            acc3.x += f01.x * g7; acc3.y += f01.y * g7;
            acc3.z += f23.x * g7; acc3.w += f23.y * g7;
        }
    }
    for (; e < end; e++) {
        uint2 a0 = g_adj[e];
        float g0 = __uint_as_float(a0.y);
        uint2 q0 = __ldg(g_Ph + (size_t)a0.x * 32 + lane);
        float2 f01 = unpack_h2(q0.x), f23 = unpack_h2(q0.y);
        acc0.x += f01.x * g0; acc0.y += f01.y * g0;
        acc0.z += f23.x * g0; acc0.w += f23.y * g0;
    }

    int b = lane >> 4;
    int c = lane & 15;
    size_t o = ((size_t)b * N + node) * 16 + c;
    float4 nf = reinterpret_cast<const float4*>(nodef)[o];
    float4 ef = reinterpret_cast<const float4*>(edgef)[o];

    float4 s;
    s.x = nf.x + ef.x + (acc0.x + acc1.x) + (acc2.x + acc3.x);
    s.y = nf.y + ef.y + (acc0.y + acc1.y) + (acc2.y + acc3.y);
    s.z = nf.z + ef.z + (acc0.z + acc1.z) + (acc2.z + acc3.z);
    s.w = nf.w + ef.w + (acc0.w + acc1.w) + (acc2.w + acc3.w);
    s.x = (s.x >= 0.f) ? s.x : 0.01f * s.x;
    s.y = (s.y >= 0.f) ? s.y : 0.01f * s.y;
    s.z = (s.z >= 0.f) ? s.z : 0.01f * s.z;
    s.w = (s.w >= 0.f) ? s.w : 0.01f * s.w;

    reinterpret_cast<float4*>(out)[o] = s;
}

// ---------------------------------------------------------------------------
extern "C" void kernel_launch(void* const* d_in, const int* in_sizes, int n_in,
                              void* d_out, int out_size)
{
    const float* prev  = (const float*)d_in[0];
    const int*   edges = (const int*)  d_in[1];
    const float* nodef = (const float*)d_in[2];
    const float* edgef = (const float*)d_in[3];
    const float* stat  = (const float*)d_in[4];
    const float* W     = (const float*)d_in[5];
    float* out = (float*)d_out;

    int E     = in_sizes[4];
    int nRows = in_sizes[0] / DD;   // B*N
    int N     = nRows / BB;

    int Epair   = (E >> 1) + 1;
    int nTransB = (nRows + 63) / 64;
    int nCountB = (Epair + 255) / 256;
    int nScanB  = (N + SCAN_B - 1) / SCAN_B;

    void* degPtr = nullptr;
    cudaGetSymbolAddress(&degPtr, g_deg);
    cudaMemsetAsync(degPtr, 0, (size_t)N * sizeof(int));

    // merged transform + count (independent, co-scheduled in one launch)
    k_phase1<<<nTransB + nCountB, 256>>>(prev, W, edges, nRows, N, E, nTransB);

    k_scan<<<nScanB, SCAN_B>>>(N);
    k_fill<<<(Epair + 255) / 256, 256>>>(edges, stat, E);

    long long th = (long long)N * 32;
    k_gather_final<<<(unsigned)((th + 255) / 256), 256>>>(nodef, edgef, out, N);
}

// round 8
// speedup vs baseline: 1.1966x; 1.1966x over previous
#include <cuda_runtime.h>
#include <cuda_fp16.h>
#include <cstdint>

#define BB 2
#define DD 64
#define MAXN 50000
#define MAXE 800000
#define SCAN_B 1024

// ---------------- static device scratch (no allocations allowed) -----------
__device__ uint2 g_Ph[(size_t)MAXN * 32];      // fp16 P, [node][batch][64]
__device__ int   g_deg[MAXN];
__device__ int   g_off[MAXN + 1];
__device__ int   g_bsum[64];
__device__ uint2 g_rank[MAXE];                 // (rank_u, rank_v) per edge
__device__ uint2 g_adj[2 * MAXE];              // (nbr, gate-bits)

// ---------------- small helpers ---------------------------------------------
__device__ __forceinline__ unsigned long long pack2(float lo, float hi) {
    unsigned long long r;
    asm("mov.b64 %0, {%1, %2};" : "=l"(r) : "f"(lo), "f"(hi));
    return r;
}
__device__ __forceinline__ float2 unpack2(unsigned long long v) {
    float2 r;
    asm("mov.b64 {%0, %1}, %2;" : "=f"(r.x), "=f"(r.y) : "l"(v));
    return r;
}
__device__ __forceinline__ void ffma2(unsigned long long& d,
                                      unsigned long long a,
                                      unsigned long long b) {
    asm("fma.rn.f32x2 %0, %1, %2, %0;" : "+l"(d) : "l"(a), "l"(b));
}
__device__ __forceinline__ unsigned pack_h2(float a, float b) {
    __half2 h = __floats2half2_rn(a, b);
    return *reinterpret_cast<unsigned*>(&h);
}
__device__ __forceinline__ float2 unpack_h2(unsigned u) {
    __half2 h = *reinterpret_cast<__half2*>(&u);
    return __half22float2(h);
}

// ---------------------------------------------------------------------------
// Transform: P = prev @ W^T (fp32 math), store fp16 interleaved.
// ---------------------------------------------------------------------------
__global__ __launch_bounds__(256)
void k_transform(const float* __restrict__ prev, const float* __restrict__ W,
                 int nRows, int N)
{
    __shared__ float As[64][66];
    __shared__ float Wt[64][64];

    int tid = threadIdx.x;
    int row0 = blockIdx.x * 64;

#pragma unroll
    for (int j = 0; j < 4; j++) {
        int f4 = tid + j * 256;
        int e = f4 >> 4, k4 = f4 & 15;
        float4 w = reinterpret_cast<const float4*>(W)[f4];
        Wt[k4 * 4 + 0][e] = w.x;
        Wt[k4 * 4 + 1][e] = w.y;
        Wt[k4 * 4 + 2][e] = w.z;
        Wt[k4 * 4 + 3][e] = w.w;
    }
#pragma unroll
    for (int j = 0; j < 4; j++) {
        int f4 = tid + j * 256;
        int r = f4 >> 4, c4 = f4 & 15;
        float4 a = make_float4(0.f, 0.f, 0.f, 0.f);
        if (row0 + r < nRows)
            a = reinterpret_cast<const float4*>(prev)[(size_t)(row0 + r) * 16 + c4];
        As[c4 * 4 + 0][r] = a.x;
        As[c4 * 4 + 1][r] = a.y;
        As[c4 * 4 + 2][r] = a.z;
        As[c4 * 4 + 3][r] = a.w;
    }
    __syncthreads();

    int colg = tid & 15;
    int rowg = tid >> 4;

    unsigned long long acc[2][4] = {};

#pragma unroll 8
    for (int k = 0; k < 64; k++) {
        const unsigned long long* ar =
            reinterpret_cast<const unsigned long long*>(&As[k][rowg * 4]);
        unsigned long long A0 = ar[0];
        unsigned long long A1 = ar[1];
        float4 w = *reinterpret_cast<const float4*>(&Wt[k][colg * 4]);
        unsigned long long w0 = pack2(w.x, w.x);
        unsigned long long w1 = pack2(w.y, w.y);
        unsigned long long w2 = pack2(w.z, w.z);
        unsigned long long w3 = pack2(w.w, w.w);
        ffma2(acc[0][0], A0, w0); ffma2(acc[0][1], A0, w1);
        ffma2(acc[0][2], A0, w2); ffma2(acc[0][3], A0, w3);
        ffma2(acc[1][0], A1, w0); ffma2(acc[1][1], A1, w1);
        ffma2(acc[1][2], A1, w2); ffma2(acc[1][3], A1, w3);
    }

#pragma unroll
    for (int p = 0; p < 2; p++) {
        float2 v0 = unpack2(acc[p][0]);
        float2 v1 = unpack2(acc[p][1]);
        float2 v2 = unpack2(acc[p][2]);
        float2 v3 = unpack2(acc[p][3]);
        int rA = row0 + rowg * 4 + p * 2;
        int rB = rA + 1;
        if (rA < nRows) {
            int b = (rA >= N) ? 1 : 0;
            int n = rA - b * N;
            g_Ph[(size_t)n * 32 + b * 16 + colg] =
                make_uint2(pack_h2(v0.x, v1.x), pack_h2(v2.x, v3.x));
        }
        if (rB < nRows) {
            int b = (rB >= N) ? 1 : 0;
            int n = rB - b * N;
            g_Ph[(size_t)n * 32 + b * 16 + colg] =
                make_uint2(pack_h2(v0.y, v1.y), pack_h2(v2.y, v3.y));
        }
    }
}

// ---------------------------------------------------------------------------
// Count + rank, 4 edges per thread (single atomic pass).
// ---------------------------------------------------------------------------
__global__ __launch_bounds__(256)
void k_count_rank(const int* __restrict__ edges, int E)
{
    int i = blockIdx.x * blockDim.x + threadIdx.x;
    int Eq = E >> 2;
    if (i < Eq) {
        int4 eA = reinterpret_cast<const int4*>(edges)[2 * i];
        int4 eB = reinterpret_cast<const int4*>(edges)[2 * i + 1];
        unsigned r0 = atomicAdd(&g_deg[eA.x], 1);
        unsigned r1 = atomicAdd(&g_deg[eA.y], 1);
        unsigned r2 = atomicAdd(&g_deg[eA.z], 1);
        unsigned r3 = atomicAdd(&g_deg[eA.w], 1);
        unsigned r4 = atomicAdd(&g_deg[eB.x], 1);
        unsigned r5 = atomicAdd(&g_deg[eB.y], 1);
        unsigned r6 = atomicAdd(&g_deg[eB.z], 1);
        unsigned r7 = atomicAdd(&g_deg[eB.w], 1);
        reinterpret_cast<uint4*>(g_rank)[2 * i]     = make_uint4(r0, r1, r2, r3);
        reinterpret_cast<uint4*>(g_rank)[2 * i + 1] = make_uint4(r4, r5, r6, r7);
    } else if (i == Eq) {
        for (int e = Eq << 2; e < E; e++) {
            int u = edges[2 * (size_t)e];
            int v = edges[2 * (size_t)e + 1];
            unsigned ru = atomicAdd(&g_deg[u], 1);
            unsigned rv = atomicAdd(&g_deg[v], 1);
            g_rank[e] = make_uint2(ru, rv);
        }
    }
}

// ---------------------------------------------------------------------------
// 3-phase scan (proven in R6).
// ---------------------------------------------------------------------------
__global__ __launch_bounds__(SCAN_B)
void k_scan_local(int N)
{
    __shared__ int sh[SCAN_B];
    int t = threadIdx.x;
    int i = blockIdx.x * SCAN_B + t;
    int d = (i < N) ? g_deg[i] : 0;
    sh[t] = d;
    __syncthreads();
    for (int s = 1; s < SCAN_B; s <<= 1) {
        int o = (t >= s) ? sh[t - s] : 0;
        __syncthreads();
        sh[t] += o;
        __syncthreads();
    }
    if (i < N) g_off[i] = sh[t] - d;
    if (t == SCAN_B - 1) g_bsum[blockIdx.x] = sh[t];
}

__global__ __launch_bounds__(64)
void k_scan_bsum(int nBlocks, int N)
{
    int t = threadIdx.x;
    int v = (t < nBlocks) ? g_bsum[t] : 0;
    __shared__ int sh[64];
    sh[t] = v;
    __syncthreads();
    for (int s = 1; s < 64; s <<= 1) {
        int o = (t >= s) ? sh[t - s] : 0;
        __syncthreads();
        sh[t] += o;
        __syncthreads();
    }
    if (t < nBlocks) g_bsum[t] = sh[t] - v;
    if (t == 63) g_off[N] = sh[63];
}

__global__ __launch_bounds__(SCAN_B)
void k_scan_add(int N)
{
    int i = blockIdx.x * SCAN_B + threadIdx.x;
    if (i < N) g_off[i] += g_bsum[blockIdx.x];
}

// ---------------------------------------------------------------------------
// Atomic-free fill, 4 edges per thread (8 offset loads + 8 stores in flight).
// ---------------------------------------------------------------------------
__global__ __launch_bounds__(256)
void k_fill(const int* __restrict__ edges, const float* __restrict__ status,
            int E)
{
    int i = blockIdx.x * blockDim.x + threadIdx.x;
    int Eq = E >> 2;
    if (i < Eq) {
        int4  eA = reinterpret_cast<const int4*>(edges)[2 * i];
        int4  eB = reinterpret_cast<const int4*>(edges)[2 * i + 1];
        uint4 rA = reinterpret_cast<const uint4*>(g_rank)[2 * i];
        uint4 rB = reinterpret_cast<const uint4*>(g_rank)[2 * i + 1];
        float4 st = reinterpret_cast<const float4*>(status)[i];
        unsigned s0 = __float_as_uint(st.x);
        unsigned s1 = __float_as_uint(st.y);
        unsigned s2 = __float_as_uint(st.z);
        unsigned s3 = __float_as_uint(st.w);
        int o0 = g_off[eA.x] + (int)rA.x;
        int o1 = g_off[eA.y] + (int)rA.y;
        int o2 = g_off[eA.z] + (int)rA.z;
        int o3 = g_off[eA.w] + (int)rA.w;
        int o4 = g_off[eB.x] + (int)rB.x;
        int o5 = g_off[eB.y] + (int)rB.y;
        int o6 = g_off[eB.z] + (int)rB.z;
        int o7 = g_off[eB.w] + (int)rB.w;
        g_adj[o0] = make_uint2((unsigned)eA.y, s0);
        g_adj[o1] = make_uint2((unsigned)eA.x, s0);
        g_adj[o2] = make_uint2((unsigned)eA.w, s1);
        g_adj[o3] = make_uint2((unsigned)eA.z, s1);
        g_adj[o4] = make_uint2((unsigned)eB.y, s2);
        g_adj[o5] = make_uint2((unsigned)eB.x, s2);
        g_adj[o6] = make_uint2((unsigned)eB.w, s3);
        g_adj[o7] = make_uint2((unsigned)eB.z, s3);
    } else if (i == Eq) {
        for (int e = Eq << 2; e < E; e++) {
            int u = edges[2 * (size_t)e];
            int v = edges[2 * (size_t)e + 1];
            uint2 r = g_rank[e];
            unsigned gb = __float_as_uint(status[e]);
            g_adj[g_off[u] + (int)r.x] = make_uint2((unsigned)v, gb);
            g_adj[g_off[v] + (int)r.y] = make_uint2((unsigned)u, gb);
        }
    }
}

// ---------------------------------------------------------------------------
// Gather + epilogue: one warp per node, 8 loads in flight, f32x2 accumulate.
// ---------------------------------------------------------------------------
__device__ __forceinline__ void acc_edge(unsigned long long& aLo,
                                         unsigned long long& aHi,
                                         uint2 q, float g)
{
    float2 f01 = unpack_h2(q.x);
    float2 f23 = unpack_h2(q.y);
    unsigned long long gg = pack2(g, g);
    ffma2(aLo, pack2(f01.x, f01.y), gg);
    ffma2(aHi, pack2(f23.x, f23.y), gg);
}

__global__ __launch_bounds__(256)
void k_gather_final(const float* __restrict__ nodef,
                    const float* __restrict__ edgef,
                    float* __restrict__ out, int N)
{
    int node = (blockIdx.x * blockDim.x + threadIdx.x) >> 5;
    if (node >= N) return;
    int lane = threadIdx.x & 31;

    int beg = __ldg(&g_off[node]);
    int end = __ldg(&g_off[node + 1]);

    unsigned long long a0L = 0, a0H = 0, a1L = 0, a1H = 0;
    unsigned long long a2L = 0, a2H = 0, a3L = 0, a3H = 0;

    int e = beg;
    for (; e + 7 < end; e += 8) {
        uint2 d0 = g_adj[e];
        uint2 d1 = g_adj[e + 1];
        uint2 d2 = g_adj[e + 2];
        uint2 d3 = g_adj[e + 3];
        uint2 d4 = g_adj[e + 4];
        uint2 d5 = g_adj[e + 5];
        uint2 d6 = g_adj[e + 6];
        uint2 d7 = g_adj[e + 7];
        uint2 q0 = __ldg(g_Ph + (size_t)d0.x * 32 + lane);
        uint2 q1 = __ldg(g_Ph + (size_t)d1.x * 32 + lane);
        uint2 q2 = __ldg(g_Ph + (size_t)d2.x * 32 + lane);
        uint2 q3 = __ldg(g_Ph + (size_t)d3.x * 32 + lane);
        uint2 q4 = __ldg(g_Ph + (size_t)d4.x * 32 + lane);
        uint2 q5 = __ldg(g_Ph + (size_t)d5.x * 32 + lane);
        uint2 q6 = __ldg(g_Ph + (size_t)d6.x * 32 + lane);
        uint2 q7 = __ldg(g_Ph + (size_t)d7.x * 32 + lane);
        acc_edge(a0L, a0H, q0, __uint_as_float(d0.y));
        acc_edge(a1L, a1H, q1, __uint_as_float(d1.y));
        acc_edge(a2L, a2H, q2, __uint_as_float(d2.y));
        acc_edge(a3L, a3H, q3, __uint_as_float(d3.y));
        acc_edge(a0L, a0H, q4, __uint_as_float(d4.y));
        acc_edge(a1L, a1H, q5, __uint_as_float(d5.y));
        acc_edge(a2L, a2H, q6, __uint_as_float(d6.y));
        acc_edge(a3L, a3H, q7, __uint_as_float(d7.y));
    }
    for (; e < end; e++) {
        uint2 d0 = g_adj[e];
        uint2 q0 = __ldg(g_Ph + (size_t)d0.x * 32 + lane);
        acc_edge(a0L, a0H, q0, __uint_as_float(d0.y));
    }

    float2 r0 = unpack2(a0L), r1 = unpack2(a1L), r2 = unpack2(a2L), r3 = unpack2(a3L);
    float2 s0 = unpack2(a0H), s1 = unpack2(a1H), s2 = unpack2(a2H), s3 = unpack2(a3H);

    int b = lane >> 4;
    int c = lane & 15;
    size_t o = ((size_t)b * N + node) * 16 + c;
    float4 nf = reinterpret_cast<const float4*>(nodef)[o];
    float4 ef = reinterpret_cast<const float4*>(edgef)[o];

    float4 s;
    s.x = nf.x + ef.x + (r0.x + r1.x) + (r2.x + r3.x);
    s.y = nf.y + ef.y + (r0.y + r1.y) + (r2.y + r3.y);
    s.z = nf.z + ef.z + (s0.x + s1.x) + (s2.x + s3.x);
    s.w = nf.w + ef.w + (s0.y + s1.y) + (s2.y + s3.y);
    s.x = (s.x >= 0.f) ? s.x : 0.01f * s.x;
    s.y = (s.y >= 0.f) ? s.y : 0.01f * s.y;
    s.z = (s.z >= 0.f) ? s.z : 0.01f * s.z;
    s.w = (s.w >= 0.f) ? s.w : 0.01f * s.w;

    reinterpret_cast<float4*>(out)[o] = s;
}

// ---------------------------------------------------------------------------
extern "C" void kernel_launch(void* const* d_in, const int* in_sizes, int n_in,
                              void* d_out, int out_size)
{
    const float* prev  = (const float*)d_in[0];
    const int*   edges = (const int*)  d_in[1];
    const float* nodef = (const float*)d_in[2];
    const float* edgef = (const float*)d_in[3];
    const float* stat  = (const float*)d_in[4];
    const float* W     = (const float*)d_in[5];
    float* out = (float*)d_out;

    int E     = in_sizes[4];
    int nRows = in_sizes[0] / DD;   // B*N
    int N     = nRows / BB;

    int Eq     = (E >> 2) + 1;
    int nScanB = (N + SCAN_B - 1) / SCAN_B;

    void* degPtr = nullptr;
    cudaGetSymbolAddress(&degPtr, g_deg);
    cudaMemsetAsync(degPtr, 0, (size_t)N * sizeof(int));

    k_count_rank<<<(Eq + 255) / 256, 256>>>(edges, E);
    k_scan_local<<<nScanB, SCAN_B>>>(N);
    k_scan_bsum <<<1, 64>>>(nScanB, N);
    k_scan_add  <<<nScanB, SCAN_B>>>(N);
    k_fill      <<<(Eq + 255) / 256, 256>>>(edges, stat, E);

    k_transform<<<(nRows + 63) / 64, 256>>>(prev, W, nRows, N);

    long long th = (long long)N * 32;
    k_gather_final<<<(unsigned)((th + 255) / 256), 256>>>(nodef, edgef, out, N);
}

// round 9
// speedup vs baseline: 1.3636x; 1.1396x over previous
#include <cuda_runtime.h>
#include <cuda_fp16.h>
#include <cstdint>

#define BB 2
#define DD 64
#define MAXN 50000
#define MAXE 800000
#define SCAN_B 1024

// ---------------- static device scratch (no allocations allowed) -----------
__device__ uint2 g_Ph[(size_t)MAXN * 32];      // fp16 P, [node][batch][64]
__device__ int   g_deg[MAXN];
__device__ int   g_off[MAXN + 1];              // block-local exclusive prefix
__device__ int   g_bsum[64];                   // per-block base (exclusive)
__device__ uint2 g_rank[MAXE];                 // (rank_u, rank_v) per edge
__device__ uint2 g_adj[2 * MAXE];              // (nbr, gate-bits)

// ---------------- small helpers ---------------------------------------------
__device__ __forceinline__ unsigned long long pack2(float lo, float hi) {
    unsigned long long r;
    asm("mov.b64 %0, {%1, %2};" : "=l"(r) : "f"(lo), "f"(hi));
    return r;
}
__device__ __forceinline__ float2 unpack2(unsigned long long v) {
    float2 r;
    asm("mov.b64 {%0, %1}, %2;" : "=f"(r.x), "=f"(r.y) : "l"(v));
    return r;
}
__device__ __forceinline__ void ffma2(unsigned long long& d,
                                      unsigned long long a,
                                      unsigned long long b) {
    asm("fma.rn.f32x2 %0, %1, %2, %0;" : "+l"(d) : "l"(a), "l"(b));
}
__device__ __forceinline__ unsigned pack_h2(float a, float b) {
    __half2 h = __floats2half2_rn(a, b);
    return *reinterpret_cast<unsigned*>(&h);
}
__device__ __forceinline__ float2 unpack_h2(unsigned u) {
    __half2 h = *reinterpret_cast<__half2*>(&u);
    return __half22float2(h);
}

// ---------------------------------------------------------------------------
// Transform: P = prev @ W^T (fp32 math), store fp16 interleaved.
// ---------------------------------------------------------------------------
__global__ __launch_bounds__(256)
void k_transform(const float* __restrict__ prev, const float* __restrict__ W,
                 int nRows, int N)
{
    __shared__ float As[64][66];
    __shared__ float Wt[64][64];

    int tid = threadIdx.x;
    int row0 = blockIdx.x * 64;

#pragma unroll
    for (int j = 0; j < 4; j++) {
        int f4 = tid + j * 256;
        int e = f4 >> 4, k4 = f4 & 15;
        float4 w = reinterpret_cast<const float4*>(W)[f4];
        Wt[k4 * 4 + 0][e] = w.x;
        Wt[k4 * 4 + 1][e] = w.y;
        Wt[k4 * 4 + 2][e] = w.z;
        Wt[k4 * 4 + 3][e] = w.w;
    }
#pragma unroll
    for (int j = 0; j < 4; j++) {
        int f4 = tid + j * 256;
        int r = f4 >> 4, c4 = f4 & 15;
        float4 a = make_float4(0.f, 0.f, 0.f, 0.f);
        if (row0 + r < nRows)
            a = reinterpret_cast<const float4*>(prev)[(size_t)(row0 + r) * 16 + c4];
        As[c4 * 4 + 0][r] = a.x;
        As[c4 * 4 + 1][r] = a.y;
        As[c4 * 4 + 2][r] = a.z;
        As[c4 * 4 + 3][r] = a.w;
    }
    __syncthreads();

    int colg = tid & 15;
    int rowg = tid >> 4;

    unsigned long long acc[2][4] = {};

#pragma unroll 8
    for (int k = 0; k < 64; k++) {
        const unsigned long long* ar =
            reinterpret_cast<const unsigned long long*>(&As[k][rowg * 4]);
        unsigned long long A0 = ar[0];
        unsigned long long A1 = ar[1];
        float4 w = *reinterpret_cast<const float4*>(&Wt[k][colg * 4]);
        unsigned long long w0 = pack2(w.x, w.x);
        unsigned long long w1 = pack2(w.y, w.y);
        unsigned long long w2 = pack2(w.z, w.z);
        unsigned long long w3 = pack2(w.w, w.w);
        ffma2(acc[0][0], A0, w0); ffma2(acc[0][1], A0, w1);
        ffma2(acc[0][2], A0, w2); ffma2(acc[0][3], A0, w3);
        ffma2(acc[1][0], A1, w0); ffma2(acc[1][1], A1, w1);
        ffma2(acc[1][2], A1, w2); ffma2(acc[1][3], A1, w3);
    }

#pragma unroll
    for (int p = 0; p < 2; p++) {
        float2 v0 = unpack2(acc[p][0]);
        float2 v1 = unpack2(acc[p][1]);
        float2 v2 = unpack2(acc[p][2]);
        float2 v3 = unpack2(acc[p][3]);
        int rA = row0 + rowg * 4 + p * 2;
        int rB = rA + 1;
        if (rA < nRows) {
            int b = (rA >= N) ? 1 : 0;
            int n = rA - b * N;
            g_Ph[(size_t)n * 32 + b * 16 + colg] =
                make_uint2(pack_h2(v0.x, v1.x), pack_h2(v2.x, v3.x));
        }
        if (rB < nRows) {
            int b = (rB >= N) ? 1 : 0;
            int n = rB - b * N;
            g_Ph[(size_t)n * 32 + b * 16 + colg] =
                make_uint2(pack_h2(v0.y, v1.y), pack_h2(v2.y, v3.y));
        }
    }
}

// ---------------------------------------------------------------------------
// Count + rank, 2 edges per thread (single atomic pass) — R6 proven shape.
// ---------------------------------------------------------------------------
__global__ __launch_bounds__(256)
void k_count_rank(const int* __restrict__ edges, int E)
{
    int i = blockIdx.x * blockDim.x + threadIdx.x;
    int Eh = E >> 1;
    if (i < Eh) {
        int4 e2 = reinterpret_cast<const int4*>(edges)[i];
        unsigned r0 = atomicAdd(&g_deg[e2.x], 1);
        unsigned r1 = atomicAdd(&g_deg[e2.y], 1);
        unsigned r2 = atomicAdd(&g_deg[e2.z], 1);
        unsigned r3 = atomicAdd(&g_deg[e2.w], 1);
        reinterpret_cast<uint4*>(g_rank)[i] = make_uint4(r0, r1, r2, r3);
    } else if (i == Eh && (E & 1)) {
        int e = E - 1;
        int u = edges[2 * (size_t)e];
        int v = edges[2 * (size_t)e + 1];
        unsigned ru = atomicAdd(&g_deg[u], 1);
        unsigned rv = atomicAdd(&g_deg[v], 1);
        g_rank[e] = make_uint2(ru, rv);
    }
}

// ---------------------------------------------------------------------------
// 2-phase scan: local prefix + block-sum scan. Bases folded into consumers.
// ---------------------------------------------------------------------------
__global__ __launch_bounds__(SCAN_B)
void k_scan_local(int N)
{
    __shared__ int sh[SCAN_B];
    int t = threadIdx.x;
    int i = blockIdx.x * SCAN_B + t;
    int d = (i < N) ? g_deg[i] : 0;
    sh[t] = d;
    __syncthreads();
    for (int s = 1; s < SCAN_B; s <<= 1) {
        int o = (t >= s) ? sh[t - s] : 0;
        __syncthreads();
        sh[t] += o;
        __syncthreads();
    }
    if (i < N) g_off[i] = sh[t] - d;          // block-local exclusive
    if (t == SCAN_B - 1) g_bsum[blockIdx.x] = sh[t];
}

__global__ __launch_bounds__(64)
void k_scan_bsum(int nBlocks)
{
    int t = threadIdx.x;
    int v = (t < nBlocks) ? g_bsum[t] : 0;
    __shared__ int sh[64];
    sh[t] = v;
    __syncthreads();
    for (int s = 1; s < 64; s <<= 1) {
        int o = (t >= s) ? sh[t - s] : 0;
        __syncthreads();
        sh[t] += o;
        __syncthreads();
    }
    if (t < nBlocks) g_bsum[t] = sh[t] - v;   // exclusive base per scan block
}

// ---------------------------------------------------------------------------
// Atomic-free fill, 2 edges per thread; absolute slot = local + bsum + rank.
// ---------------------------------------------------------------------------
__global__ __launch_bounds__(256)
void k_fill(const int* __restrict__ edges, const float* __restrict__ status,
            int E)
{
    int i = blockIdx.x * blockDim.x + threadIdx.x;
    int Eh = E >> 1;
    if (i < Eh) {
        int4  e2 = reinterpret_cast<const int4*>(edges)[i];
        uint4 r2 = reinterpret_cast<const uint4*>(g_rank)[i];
        float2 st = reinterpret_cast<const float2*>(status)[i];
        unsigned g0 = __float_as_uint(st.x);
        unsigned g1 = __float_as_uint(st.y);
        int o0 = g_off[e2.x] + g_bsum[e2.x >> 10] + (int)r2.x;
        int o1 = g_off[e2.y] + g_bsum[e2.y >> 10] + (int)r2.y;
        int o2 = g_off[e2.z] + g_bsum[e2.z >> 10] + (int)r2.z;
        int o3 = g_off[e2.w] + g_bsum[e2.w >> 10] + (int)r2.w;
        g_adj[o0] = make_uint2((unsigned)e2.y, g0);
        g_adj[o1] = make_uint2((unsigned)e2.x, g0);
        g_adj[o2] = make_uint2((unsigned)e2.w, g1);
        g_adj[o3] = make_uint2((unsigned)e2.z, g1);
    } else if (i == Eh && (E & 1)) {
        int e = E - 1;
        int u = edges[2 * (size_t)e];
        int v = edges[2 * (size_t)e + 1];
        uint2 r = g_rank[e];
        unsigned gb = __float_as_uint(status[e]);
        g_adj[g_off[u] + g_bsum[u >> 10] + (int)r.x] = make_uint2((unsigned)v, gb);
        g_adj[g_off[v] + g_bsum[v >> 10] + (int)r.y] = make_uint2((unsigned)u, gb);
    }
}

// ---------------------------------------------------------------------------
// Gather + epilogue: one warp per node, 8 loads in flight (R6 inner loop).
// 128-thread blocks for higher reg-limited occupancy.
// end = beg + deg (avoids g_off[N] and the base-add pass entirely).
// ---------------------------------------------------------------------------
__global__ __launch_bounds__(128)
void k_gather_final(const float* __restrict__ nodef,
                    const float* __restrict__ edgef,
                    float* __restrict__ out, int N)
{
    int node = (blockIdx.x * blockDim.x + threadIdx.x) >> 5;
    if (node >= N) return;
    int lane = threadIdx.x & 31;

    int beg = __ldg(&g_off[node]) + __ldg(&g_bsum[node >> 10]);
    int end = beg + __ldg(&g_deg[node]);

    float4 acc0 = make_float4(0.f, 0.f, 0.f, 0.f);
    float4 acc1 = make_float4(0.f, 0.f, 0.f, 0.f);
    float4 acc2 = make_float4(0.f, 0.f, 0.f, 0.f);
    float4 acc3 = make_float4(0.f, 0.f, 0.f, 0.f);

    int e = beg;
    for (; e + 7 < end; e += 8) {
        uint2 a0 = g_adj[e];
        uint2 a1 = g_adj[e + 1];
        uint2 a2 = g_adj[e + 2];
        uint2 a3 = g_adj[e + 3];
        uint2 a4 = g_adj[e + 4];
        uint2 a5 = g_adj[e + 5];
        uint2 a6 = g_adj[e + 6];
        uint2 a7 = g_adj[e + 7];
        uint2 q0 = __ldg(g_Ph + (size_t)a0.x * 32 + lane);
        uint2 q1 = __ldg(g_Ph + (size_t)a1.x * 32 + lane);
        uint2 q2 = __ldg(g_Ph + (size_t)a2.x * 32 + lane);
        uint2 q3 = __ldg(g_Ph + (size_t)a3.x * 32 + lane);
        uint2 q4 = __ldg(g_Ph + (size_t)a4.x * 32 + lane);
        uint2 q5 = __ldg(g_Ph + (size_t)a5.x * 32 + lane);
        uint2 q6 = __ldg(g_Ph + (size_t)a6.x * 32 + lane);
        uint2 q7 = __ldg(g_Ph + (size_t)a7.x * 32 + lane);
        float g0 = __uint_as_float(a0.y);
        float g1 = __uint_as_float(a1.y);
        float g2 = __uint_as_float(a2.y);
        float g3 = __uint_as_float(a3.y);
        float g4 = __uint_as_float(a4.y);
        float g5 = __uint_as_float(a5.y);
        float g6 = __uint_as_float(a6.y);
        float g7 = __uint_as_float(a7.y);
        {
            float2 f01 = unpack_h2(q0.x), f23 = unpack_h2(q0.y);
            acc0.x += f01.x * g0; acc0.y += f01.y * g0;
            acc0.z += f23.x * g0; acc0.w += f23.y * g0;
        }
        {
            float2 f01 = unpack_h2(q1.x), f23 = unpack_h2(q1.y);
            acc1.x += f01.x * g1; acc1.y += f01.y * g1;
            acc1.z += f23.x * g1; acc1.w += f23.y * g1;
        }
        {
            float2 f01 = unpack_h2(q2.x), f23 = unpack_h2(q2.y);
            acc2.x += f01.x * g2; acc2.y += f01.y * g2;
            acc2.z += f23.x * g2; acc2.w += f23.y * g2;
        }
        {
            float2 f01 = unpack_h2(q3.x), f23 = unpack_h2(q3.y);
            acc3.x += f01.x * g3; acc3.y += f01.y * g3;
            acc3.z += f23.x * g3; acc3.w += f23.y * g3;
        }
        {
            float2 f01 = unpack_h2(q4.x), f23 = unpack_h2(q4.y);
            acc0.x += f01.x * g4; acc0.y += f01.y * g4;
            acc0.z += f23.x * g4; acc0.w += f23.y * g4;
        }
        {
            float2 f01 = unpack_h2(q5.x), f23 = unpack_h2(q5.y);
            acc1.x += f01.x * g5; acc1.y += f01.y * g5;
            acc1.z += f23.x * g5; acc1.w += f23.y * g5;
        }
        {
            float2 f01 = unpack_h2(q6.x), f23 = unpack_h2(q6.y);
            acc2.x += f01.x * g6; acc2.y += f01.y * g6;
            acc2.z += f23.x * g6; acc2.w += f23.y * g6;
        }
        {
            float2 f01 = unpack_h2(q7.x), f23 = unpack_h2(q7.y);
            acc3.x += f01.x * g7; acc3.y += f01.y * g7;
            acc3.z += f23.x * g7; acc3.w += f23.y * g7;
        }
    }
    for (; e < end; e++) {
        uint2 a0 = g_adj[e];
        float g0 = __uint_as_float(a0.y);
        uint2 q0 = __ldg(g_Ph + (size_t)a0.x * 32 + lane);
        float2 f01 = unpack_h2(q0.x), f23 = unpack_h2(q0.y);
        acc0.x += f01.x * g0; acc0.y += f01.y * g0;
        acc0.z += f23.x * g0; acc0.w += f23.y * g0;
    }

    int b = lane >> 4;
    int c = lane & 15;
    size_t o = ((size_t)b * N + node) * 16 + c;
    float4 nf = reinterpret_cast<const float4*>(nodef)[o];
    float4 ef = reinterpret_cast<const float4*>(edgef)[o];

    float4 s;
    s.x = nf.x + ef.x + (acc0.x + acc1.x) + (acc2.x + acc3.x);
    s.y = nf.y + ef.y + (acc0.y + acc1.y) + (acc2.y + acc3.y);
    s.z = nf.z + ef.z + (acc0.z + acc1.z) + (acc2.z + acc3.z);
    s.w = nf.w + ef.w + (acc0.w + acc1.w) + (acc2.w + acc3.w);
    s.x = (s.x >= 0.f) ? s.x : 0.01f * s.x;
    s.y = (s.y >= 0.f) ? s.y : 0.01f * s.y;
    s.z = (s.z >= 0.f) ? s.z : 0.01f * s.z;
    s.w = (s.w >= 0.f) ? s.w : 0.01f * s.w;

    reinterpret_cast<float4*>(out)[o] = s;
}

// ---------------------------------------------------------------------------
extern "C" void kernel_launch(void* const* d_in, const int* in_sizes, int n_in,
                              void* d_out, int out_size)
{
    const float* prev  = (const float*)d_in[0];
    const int*   edges = (const int*)  d_in[1];
    const float* nodef = (const float*)d_in[2];
    const float* edgef = (const float*)d_in[3];
    const float* stat  = (const float*)d_in[4];
    const float* W     = (const float*)d_in[5];
    float* out = (float*)d_out;

    int E     = in_sizes[4];
    int nRows = in_sizes[0] / DD;   // B*N
    int N     = nRows / BB;

    int Epair  = (E >> 1) + 1;
    int nScanB = (N + SCAN_B - 1) / SCAN_B;

    void* degPtr = nullptr;
    cudaGetSymbolAddress(&degPtr, g_deg);
    cudaMemsetAsync(degPtr, 0, (size_t)N * sizeof(int));

    k_count_rank<<<(Epair + 255) / 256, 256>>>(edges, E);
    k_scan_local<<<nScanB, SCAN_B>>>(N);
    k_scan_bsum <<<1, 64>>>(nScanB);
    k_fill      <<<(Epair + 255) / 256, 256>>>(edges, stat, E);

    k_transform<<<(nRows + 63) / 64, 256>>>(prev, W, nRows, N);

    long long th = (long long)N * 32;
    k_gather_final<<<(unsigned)((th + 127) / 128), 128>>>(nodef, edgef, out, N);
}